// round 8
// baseline (speedup 1.0000x reference)
#include <cuda_runtime.h>
#include <math.h>

#define NEGV (-1e30f)
#define LN2F 0.6931471805599453f

// scratch (no cudaMalloc allowed)
__device__ float g_loss[4096];
__device__ unsigned int g_ctr;   // wraps back to 0 every launch via atomicInc

__device__ __forceinline__ float ex2(float x) {
    float r; asm("ex2.approx.f32 %0, %1;" : "=f"(r) : "f"(x)); return r;
}
__device__ __forceinline__ float lg2(float x) {
    float r; asm("lg2.approx.f32 %0, %1;" : "=f"(r) : "f"(x)); return r;
}

// ---------------------------------------------------------------------------
// Fused kernel:
//   blocks [0, ctcBlocks)         : CTC forward (log2 domain, 1 barrier / 2 steps)
//   blocks [ctcBlocks, gridDim.x) : log + transpose  out[t,b,c] = log(p[b,t,c])
// ---------------------------------------------------------------------------
__global__ void __launch_bounds__(256)
ctc_fused_kernel(const float* __restrict__ p,      // [B,T,C]
                 const int* __restrict__ labels,   // [B,L]
                 const int* __restrict__ in_len,   // [B]
                 const int* __restrict__ lab_len,  // [B]
                 float* __restrict__ out,          // [T,B,C] (+ loss at end)
                 int T, int B, int C, int L,
                 int ctcBlocks, long long loss_idx) {
    if ((int)blockIdx.x >= ctcBlocks) {
        // ---------------- log + transpose (float4) --------------------------
        const int c4w = C >> 2;
        const long long total4 = (long long)T * B * c4w;
        const float4* __restrict__ p4 = (const float4*)p;
        float4* __restrict__ o4 = (float4*)out;
        const long long stride = (long long)(gridDim.x - ctcBlocks) * blockDim.x;
        for (long long v = (long long)(blockIdx.x - ctcBlocks) * blockDim.x + threadIdx.x;
             v < total4; v += stride) {
            int c4 = (int)(v % c4w);
            long long rr = v / c4w;          // rr = t*B + b
            int b = (int)(rr % B);
            long long t = rr / B;
            float4 x = p4[((long long)b * T + t) * c4w + c4];
            float4 y;
            y.x = __logf(x.x); y.y = __logf(x.y);
            y.z = __logf(x.z); y.w = __logf(x.w);
            o4[v] = y;
        }
        return;
    }

    // ---------------- CTC forward, log2 domain, 2 steps per barrier ---------
    // Thread tid owns states 2tid (even/blank) and 2tid+1 (odd/label);
    // last thread also owns state 2L. Step t needs left's odd alpha; for the
    // second step of each pair we compute the left neighbor's odd update
    // redundantly (bitwise identical to its own), so no sync is needed.
    __shared__ float bnd[2][8][4];   // [parity][warp][{ao31, ae31, ao30}]
    __shared__ float sA[513];

    const int b    = blockIdx.x;
    const int tid  = threadIdx.x;
    const int w    = tid >> 5;
    const int lane = tid & 31;
    const int last = blockDim.x - 1;

    int il = in_len[b];  il = il < 1 ? 1 : (il > T ? T : il);
    int ll = lab_len[b]; ll = ll < 1 ? 1 : (ll > L ? L : ll);

    const int  lab   = labels[b * L + tid];
    const bool skip  = (tid > 0) && (lab != labels[b * L + tid - 1]);
    const int  labL  = (tid > 0) ? labels[b * L + tid - 1] : 0;
    const bool skipL = (tid > 1) && (labels[b * L + tid - 1] != labels[b * L + tid - 2]);

    const float* __restrict__ pbase = p + (long long)b * T * C;   // blank col 0
    const float* __restrict__ plabp = pbase + lab;
    const float* __restrict__ plabL = pbase + labL;
    const bool need_l = (lane == 0) && (w > 0);

    // ---- t = 0 ----
    float ae, ao, a5 = NEGV;
    {
        float pb0 = __ldg(pbase);
        float pl0 = __ldg(plabp);
        ae = (tid == 0) ? lg2(pb0) : NEGV;
        ao = (tid == 0) ? lg2(pl0) : NEGV;
        if (lane == 31) { bnd[0][w][0] = ao; bnd[0][w][1] = ae; }
        if (lane == 30) { bnd[0][w][2] = ao; }
    }

    // prefetch slots: value for step t lives in slot t&7; preload t=1..8
    float rpb[8], rpl[8], rpL[8];
    #pragma unroll
    for (int j = 0; j < 8; ++j) {
        int tt = 1 + j; if (tt > il - 1) tt = il - 1;
        rpb[(1 + j) & 7] = __ldg(pbase + (long long)tt * C);
        rpl[(1 + j) & 7] = __ldg(plabp + (long long)tt * C);
        if (need_l) rpL[(1 + j) & 7] = __ldg(plabL + (long long)tt * C);
    }

    // ---- main loop: pairs of steps, one barrier per pair ----
    for (int tb = 1; tb < il; tb += 8) {          // tb & 7 == 1 always
        #pragma unroll
        for (int g = 0; g < 4; ++g) {
            const int t = tb + 2 * g;
            if (t >= il) break;                   // il uniform per block
            const int s0 = (1 + 2 * g) & 7;       // slot of t
            const int s1 = (2 + 2 * g) & 7;       // slot of t+1
            const int gp = g & 1;                 // boundary parity to read

            __syncthreads();                      // prev pair's bnd writes visible

            float ao31 = NEGV, ae31 = NEGV, ao30 = NEGV;
            if (w > 0 && lane < 2) {
                ao31 = bnd[gp][w - 1][0];
                if (lane == 0) { ae31 = bnd[gp][w - 1][1]; ao30 = bnd[gp][w - 1][2]; }
            }

            float pb0 = rpb[s0], pl0 = rpl[s0], pll0 = rpL[s0];
            {   // refill slot s0 with step t+8
                int tp = t + 8; if (tp > il - 1) tp = il - 1;
                rpb[s0] = __ldg(pbase + (long long)tp * C);
                rpl[s0] = __ldg(plabp + (long long)tp * C);
                if (need_l) rpL[s0] = __ldg(plabL + (long long)tp * C);
            }

            // gather left-neighbor old state
            float aol  = __shfl_up_sync(0xffffffffu, ao, 1);
            float ael  = __shfl_up_sync(0xffffffffu, ae, 1);
            float aoll = __shfl_up_sync(0xffffffffu, ao, 2);
            float pll  = __shfl_up_sync(0xffffffffu, pl0, 1);
            if (lane == 0) { aol = ao31; ael = ae31; aoll = ao30; pll = pll0; }
            if (lane == 1) { aoll = ao31; }

            // ---- step t: own states ----
            float me = fmaxf(ae, aol);
            float ve = me + lg2((1.0f + ex2(fminf(ae, aol) - me)) * pb0);
            float a2 = skip ? aol : NEGV;
            float mo = fmaxf(ao, fmaxf(ae, a2));
            float vo = mo + lg2((ex2(ao - mo) + ex2(ae - mo) + ex2(a2 - mo)) * pl0);
            if (tid == last) {
                float m5 = fmaxf(a5, ao);
                a5 = m5 + lg2((1.0f + ex2(fminf(a5, ao) - m5)) * pb0);
            }
            // ---- step t: left neighbor's odd state (redundant, bit-exact) ----
            float a2l = skipL ? aoll : NEGV;
            float mL  = fmaxf(aol, fmaxf(ael, a2l));
            float oL  = mL + lg2((ex2(aol - mL) + ex2(ael - mL) + ex2(a2l - mL)) * pll);
            if (tid == 0) oL = NEGV;              // no left neighbor

            float ae1 = ve, ao1 = vo;

            if (t + 1 < il) {
                float pb1 = rpb[s1], pl1 = rpl[s1];
                {   // refill slot s1 with step t+9
                    int tp = t + 9; if (tp > il - 1) tp = il - 1;
                    rpb[s1] = __ldg(pbase + (long long)tp * C);
                    rpl[s1] = __ldg(plabp + (long long)tp * C);
                    if (need_l) rpL[s1] = __ldg(plabL + (long long)tp * C);
                }
                // ---- step t+1: purely local ----
                float me2 = fmaxf(ae1, oL);
                ae = me2 + lg2((1.0f + ex2(fminf(ae1, oL) - me2)) * pb1);
                float a22 = skip ? oL : NEGV;
                float mo2 = fmaxf(ao1, fmaxf(ae1, a22));
                ao = mo2 + lg2((ex2(ao1 - mo2) + ex2(ae1 - mo2) + ex2(a22 - mo2)) * pl1);
                if (tid == last) {
                    float m5 = fmaxf(a5, ao1);
                    a5 = m5 + lg2((1.0f + ex2(fminf(a5, ao1) - m5)) * pb1);
                }
                // boundary for next pair
                if (lane == 31) { bnd[gp ^ 1][w][0] = ao; bnd[gp ^ 1][w][1] = ae; }
                if (lane == 30) { bnd[gp ^ 1][w][2] = ao; }
            } else {
                ae = ae1; ao = ao1;               // final odd step; loop ends
            }
        }
    }

    // ---- finalize: dump alpha, loss, fused mean via atomic counter ---------
    __syncthreads();
    sA[2 * tid]     = ae;
    sA[2 * tid + 1] = ao;
    if (tid == last) sA[512] = a5;
    __syncthreads();

    if (tid == 0) {
        float e1 = sA[2 * ll - 1];
        float e2 = sA[2 * ll];
        float m  = fmaxf(e1, e2);
        float l2 = m + lg2(ex2(e1 - m) + ex2(e2 - m));
        g_loss[b] = -l2 * LN2F;
        __threadfence();
        unsigned int old = atomicInc(&g_ctr, (unsigned)(B - 1));   // wraps to 0
        if (old == (unsigned)(B - 1)) {
            __threadfence();
            volatile float* gl = g_loss;
            float s = 0.f;
            for (int i = 0; i < B; ++i) s += gl[i];
            out[loss_idx] = s / (float)B;
        }
    }
}

// ---------------------------------------------------------------------------
extern "C" void kernel_launch(void* const* d_in, const int* in_sizes, int n_in,
                              void* d_out, int out_size) {
    const int*   y_true = (const int*)  d_in[0];  // [B, L]
    const float* y_pred = (const float*)d_in[1];  // [B, T, C]
    const int*   il     = (const int*)  d_in[2];  // [B]
    const int*   ll     = (const int*)  d_in[3];  // [B]

    const int B = in_sizes[2];
    const int L = in_sizes[0] / B;                // 256
    const int C = 128;                            // fixed for this problem
    const int T = in_sizes[1] / (B * C);
    float* out = (float*)d_out;

    const int ctcBlocks   = B;                    // one block per batch element
    const int transBlocks = 1408;                 // fill remaining SMs

    ctc_fused_kernel<<<ctcBlocks + transBlocks, L>>>(
        y_pred, y_true, il, ll, out, T, B, C, L,
        ctcBlocks, (long long)out_size - 1);
}

// round 10
// speedup vs baseline: 1.0077x; 1.0077x over previous
#include <cuda_runtime.h>
#include <math.h>

#define NEGV (-1e30f)
#define LN2F 0.6931471805599453f
#define DPRE 8

// scratch (no cudaMalloc allowed)
__device__ float g_loss[4096];
__device__ unsigned int g_ctr;   // wraps back to 0 every launch via atomicInc

__device__ __forceinline__ float ex2(float x) {
    float r; asm("ex2.approx.f32 %0, %1;" : "=f"(r) : "f"(x)); return r;
}
__device__ __forceinline__ float lg2(float x) {
    float r; asm("lg2.approx.f32 %0, %1;" : "=f"(r) : "f"(x)); return r;
}

// ---------------------------------------------------------------------------
// Fused kernel (blockDim = 128):
//   blocks [0, ctcBlocks)         : CTC forward (log2 domain, 4 states/thread)
//   blocks [ctcBlocks, gridDim.x) : log + transpose  out[t,b,c] = log(p[b,t,c])
// ---------------------------------------------------------------------------
__global__ void __launch_bounds__(128)
ctc_fused_kernel(const float* __restrict__ p,      // [B,T,C]
                 const int* __restrict__ labels,   // [B,L]
                 const int* __restrict__ in_len,   // [B]
                 const int* __restrict__ lab_len,  // [B]
                 float* __restrict__ out,          // [T,B,C] (+ loss at end)
                 int T, int B, int C, int L,
                 int ctcBlocks, long long loss_idx) {
    if ((int)blockIdx.x >= ctcBlocks) {
        // ---------------- log + transpose (float4) --------------------------
        const int c4w = C >> 2;
        const long long total4 = (long long)T * B * c4w;
        const float4* __restrict__ p4 = (const float4*)p;
        float4* __restrict__ o4 = (float4*)out;
        const long long stride = (long long)(gridDim.x - ctcBlocks) * blockDim.x;
        for (long long v = (long long)(blockIdx.x - ctcBlocks) * blockDim.x + threadIdx.x;
             v < total4; v += stride) {
            int c4 = (int)(v % c4w);
            long long rr = v / c4w;          // rr = t*B + b
            int b = (int)(rr % B);
            long long t = rr / B;
            float4 x = p4[((long long)b * T + t) * c4w + c4];
            float4 y;
            y.x = __logf(x.x); y.y = __logf(x.y);
            y.z = __logf(x.z); y.w = __logf(x.w);
            o4[v] = y;
        }
        return;
    }

    // ---------------- CTC forward, log2 domain, 4 states / thread -----------
    // Thread tid owns states 4tid (even), 4tid+1 (odd, label 2tid),
    // 4tid+2 (even), 4tid+3 (odd, label 2tid+1). Thread 127 also owns
    // state 512 (final blank). Only cross-thread dep: left's a3 (state 4tid-1),
    // via shfl + parity-buffered smem boundary, 1 barrier per timestep.
    __shared__ float bnd[2][4];
    __shared__ float sA[513];

    const int b    = blockIdx.x;
    const int tid  = threadIdx.x;
    const int w    = tid >> 5;
    const int lane = tid & 31;
    const int last = blockDim.x - 1;

    int il = in_len[b];  il = il < 1 ? 1 : (il > T ? T : il);
    int ll = lab_len[b]; ll = ll < 1 ? 1 : (ll > L ? L : ll);

    const int  lab0  = labels[b * L + 2 * tid];
    const int  lab1  = labels[b * L + 2 * tid + 1];
    const bool skip1 = (tid > 0) && (lab0 != labels[b * L + 2 * tid - 1]);
    const bool skip3 = (lab1 != lab0);

    const float* __restrict__ pbase = p + (long long)b * T * C;   // blank col 0
    const float* __restrict__ pl0p  = pbase + lab0;
    const float* __restrict__ pl1p  = pbase + lab1;

    // ---- t = 0 ----
    float a0, a1, a2 = NEGV, a3 = NEGV, a5 = NEGV;
    {
        float pb0 = __ldg(pbase);
        float pl0 = __ldg(pl0p);
        a0 = (tid == 0) ? lg2(pb0) : NEGV;
        a1 = (tid == 0) ? lg2(pl0) : NEGV;
        if (lane == 31) bnd[1][w] = a3;     // parity for t=1 (NEGV)
    }

    // depth-8 prefetch, 3 streams; slot j holds step tb+j
    float rpb[DPRE], rl0[DPRE], rl1[DPRE];
    #pragma unroll
    for (int j = 0; j < DPRE; ++j) {
        int tt = 1 + j; if (tt > il - 1) tt = il - 1;
        rpb[j] = __ldg(pbase + (long long)tt * C);
        rl0[j] = __ldg(pl0p  + (long long)tt * C);
        rl1[j] = __ldg(pl1p  + (long long)tt * C);
    }
    __syncthreads();

    // ---- t = 1 .. il-1 (il uniform per block) ----
    for (int tb = 1; tb < il; tb += DPRE) {
        #pragma unroll
        for (int j = 0; j < DPRE; ++j) {
            int t = tb + j;
            if (t >= il) break;              // uniform across block

            float pb  = rpb[j];
            float pl0 = rl0[j];
            float pl1 = rl1[j];

            // left neighbor's old a3 (state 4tid-1)
            float aL = __shfl_up_sync(0xffffffffu, a3, 1);
            if (lane == 0) aL = (w > 0) ? bnd[t & 1][w - 1] : NEGV;

            // pair (n0, n1) around shared max of {a0, a1, aL}
            float m01 = fmaxf(fmaxf(a0, a1), aL);
            float x0  = ex2(a0 - m01);
            float x1a = ex2(a1 - m01);
            float xL  = ex2(aL - m01);
            float n0 = m01 + lg2((x0 + xL) * pb);
            float n1 = m01 + lg2((x1a + x0 + (skip1 ? xL : 0.0f)) * pl0);

            // pair (n2, n3) around shared max of {a1, a2, a3}
            float m23 = fmaxf(fmaxf(a2, a3), a1);
            float x1b = ex2(a1 - m23);
            float x2  = ex2(a2 - m23);
            float x3  = ex2(a3 - m23);
            float n2 = m23 + lg2((x2 + x1b) * pb);
            float n3 = m23 + lg2((x3 + x2 + (skip3 ? x1b : 0.0f)) * pl1);

            // state 512 (final blank), last thread, uses OLD a3
            if (tid == last) {
                float m5 = fmaxf(a5, a3);
                a5 = fmaxf(m5 + lg2((ex2(a5 - m5) + ex2(a3 - m5)) * pb), NEGV);
            }

            // clamp: never let -inf (from fully-flushed sums) enter the state
            a0 = fmaxf(n0, NEGV);
            a1 = fmaxf(n1, NEGV);
            a2 = fmaxf(n2, NEGV);
            a3 = fmaxf(n3, NEGV);

            if (lane == 31) bnd[(t + 1) & 1][w] = a3;

            // refill slot with step t + DPRE
            int tp = t + DPRE; if (tp > il - 1) tp = il - 1;
            rpb[j] = __ldg(pbase + (long long)tp * C);
            rl0[j] = __ldg(pl0p  + (long long)tp * C);
            rl1[j] = __ldg(pl1p  + (long long)tp * C);

            __syncthreads();
        }
    }

    // ---- finalize: dump alpha, loss, fused mean via atomic counter ---------
    sA[4 * tid]     = a0;
    sA[4 * tid + 1] = a1;
    sA[4 * tid + 2] = a2;
    sA[4 * tid + 3] = a3;
    if (tid == last) sA[512] = a5;
    __syncthreads();

    if (tid == 0) {
        float e1 = sA[2 * ll - 1];
        float e2 = sA[2 * ll];
        float m  = fmaxf(e1, e2);
        float l2 = m + lg2(ex2(e1 - m) + ex2(e2 - m));
        g_loss[b] = -l2 * LN2F;
        __threadfence();
        unsigned int old = atomicInc(&g_ctr, (unsigned)(B - 1));   // wraps to 0
        if (old == (unsigned)(B - 1)) {
            __threadfence();
            volatile float* gl = g_loss;
            float s = 0.f;
            for (int i = 0; i < B; ++i) s += gl[i];
            out[loss_idx] = s / (float)B;
        }
    }
}

// ---------------------------------------------------------------------------
extern "C" void kernel_launch(void* const* d_in, const int* in_sizes, int n_in,
                              void* d_out, int out_size) {
    const int*   y_true = (const int*)  d_in[0];  // [B, L]
    const float* y_pred = (const float*)d_in[1];  // [B, T, C]
    const int*   il     = (const int*)  d_in[2];  // [B]
    const int*   ll     = (const int*)  d_in[3];  // [B]

    const int B = in_sizes[2];
    const int L = in_sizes[0] / B;                // 256
    const int C = 128;                            // fixed for this problem
    const int T = in_sizes[1] / (B * C);
    float* out = (float*)d_out;

    const int ctcBlocks   = B;                    // one block per batch element
    const int transBlocks = 2816;                 // fill remaining SMs (128-thr blocks)

    ctc_fused_kernel<<<ctcBlocks + transBlocks, 128>>>(
        y_pred, y_true, il, ll, out, T, B, C, L,
        ctcBlocks, (long long)out_size - 1);
}

// round 11
// speedup vs baseline: 1.5400x; 1.5283x over previous
#include <cuda_runtime.h>
#include <math.h>

#define NEGV (-1e30f)
#define LN2F 0.6931471805599453f
#define DPRE 8

// scratch (no cudaMalloc allowed)
__device__ float g_loss[4096];
__device__ unsigned int g_ctr;   // wraps back to 0 every launch via atomicInc

__device__ __forceinline__ float ex2(float x) {
    float r; asm("ex2.approx.f32 %0, %1;" : "=f"(r) : "f"(x)); return r;
}
__device__ __forceinline__ float lg2(float x) {
    float r; asm("lg2.approx.f32 %0, %1;" : "=f"(r) : "f"(x)); return r;
}
#define BAR_SYNC(id)   asm volatile("bar.sync %0, 64;"   :: "r"(id) : "memory")
#define BAR_ARRIVE(id) asm volatile("bar.arrive %0, 64;" :: "r"(id) : "memory")

// ---------------------------------------------------------------------------
// Fused kernel (blockDim = 256):
//   blocks [0, ctcBlocks)         : CTC forward (log2 domain, named-barrier
//                                   producer/consumer pipeline across warps)
//   blocks [ctcBlocks, gridDim.x) : log + transpose  out[t,b,c] = log(p[b,t,c])
// ---------------------------------------------------------------------------
__global__ void __launch_bounds__(256)
ctc_fused_kernel(const float* __restrict__ p,      // [B,T,C]
                 const int* __restrict__ labels,   // [B,L]
                 const int* __restrict__ in_len,   // [B]
                 const int* __restrict__ lab_len,  // [B]
                 float* __restrict__ out,          // [T,B,C] (+ loss at end)
                 int T, int B, int C, int L,
                 int ctcBlocks, long long loss_idx) {
    if ((int)blockIdx.x >= ctcBlocks) {
        // ---------------- log + transpose (float4) --------------------------
        const int c4w = C >> 2;
        const long long total4 = (long long)T * B * c4w;
        const float4* __restrict__ p4 = (const float4*)p;
        float4* __restrict__ o4 = (float4*)out;
        const long long stride = (long long)(gridDim.x - ctcBlocks) * blockDim.x;
        for (long long v = (long long)(blockIdx.x - ctcBlocks) * blockDim.x + threadIdx.x;
             v < total4; v += stride) {
            int c4 = (int)(v % c4w);
            long long rr = v / c4w;          // rr = t*B + b
            int b = (int)(rr % B);
            long long t = rr / B;
            float4 x = p4[((long long)b * T + t) * c4w + c4];
            float4 y;
            y.x = __logf(x.x); y.y = __logf(x.y);
            y.z = __logf(x.z); y.w = __logf(x.w);
            o4[v] = y;
        }
        return;
    }

    // ---------------- CTC forward, log2 domain, warp pipeline ---------------
    // Thread tid owns states 2tid (even/blank) and 2tid+1 (odd/label);
    // the last thread also owns state 2L (final blank).
    // Cross-warp dep (lane31's odd alpha -> next warp's lane0) flows through a
    // single smem slot per pair, guarded by named FULL/EMPTY barriers:
    //   pair (w, w+1): FULL id = 1+w, EMPTY id = 9+w, count 64.
    // Producer (w):  compute -> bar.sync(EMPTY) -> write bnd[w] -> bar.arrive(FULL)
    // Consumer (w+1): bar.sync(FULL) -> read bnd[w] -> bar.arrive(EMPTY)
    // Strict alternation is enforced by the data dependence; warps pipeline
    // with <=1-step pairwise skew. No block-wide barrier in the loop.
    __shared__ float bnd[8];
    __shared__ float sA[513];

    const int b    = blockIdx.x;
    const int tid  = threadIdx.x;
    const int w    = tid >> 5;
    const int lane = tid & 31;
    const int last = blockDim.x - 1;

    int il = in_len[b];  il = il < 1 ? 1 : (il > T ? T : il);
    int ll = lab_len[b]; ll = ll < 1 ? 1 : (ll > L ? L : ll);

    const int  lab  = labels[b * L + tid];
    const bool skip = (tid > 0) && (lab != labels[b * L + tid - 1]);

    const float* __restrict__ pbase = p + (long long)b * T * C;   // blank col 0
    const float* __restrict__ plabp = pbase + lab;

    const int FULL_c  = w;          // consumer's FULL barrier id (pair w-1)
    const int EMPTY_c = 8 + w;      // consumer's EMPTY barrier id (pair w-1)
    const int FULL_p  = 1 + w;      // producer's FULL barrier id (pair w)
    const int EMPTY_p = 9 + w;      // producer's EMPTY barrier id (pair w)

    // ---- t = 0 ----
    float ae, ao, a5 = NEGV;
    {
        float pb0 = __ldg(pbase);
        float pl0 = __ldg(plabp);
        ae = (tid == 0) ? lg2(pb0) : NEGV;
        ao = (tid == 0) ? lg2(pl0) : NEGV;
        if (w < 7) {
            if (lane == 31) bnd[w] = ao;    // value consumed at t = 1
            BAR_ARRIVE(FULL_p);
        }
    }

    // depth-8 prefetch of (blank, label) streams; slot j holds step tb+j
    float rpb[DPRE], rpl[DPRE];
    #pragma unroll
    for (int j = 0; j < DPRE; ++j) {
        int tt = 1 + j; if (tt > il - 1) tt = il - 1;
        rpb[j] = __ldg(pbase + (long long)tt * C);
        rpl[j] = __ldg(plabp + (long long)tt * C);
    }

    // ---- t = 1 .. il-1 (il uniform per block) ----
    for (int tb = 1; tb < il; tb += DPRE) {
        #pragma unroll
        for (int j = 0; j < DPRE; ++j) {
            int t = tb + j;
            if (t >= il) break;              // uniform across block

            float pb = rpb[j];
            float pl = rpl[j];

            // obtain left neighbor's old odd alpha (state 2tid-1)
            float a_ol = __shfl_up_sync(0xffffffffu, ao, 1);
            if (w > 0) {
                BAR_SYNC(FULL_c);            // producer's value for step t ready
                if (lane == 0) a_ol = bnd[w - 1];
                BAR_ARRIVE(EMPTY_c);         // slot consumed
            } else if (lane == 0) {
                a_ol = NEGV;
            }

            // even state 2tid: lse2(ae, a_ol), prob folded into lg2
            float me = fmaxf(ae, a_ol);
            float ve = me + lg2((1.0f + ex2(fminf(ae, a_ol) - me)) * pb);
            // odd state 2tid+1: lse3(ao, ae, skip ? a_ol), prob folded
            float a2 = skip ? a_ol : NEGV;
            float mo = fmaxf(ao, fmaxf(ae, a2));
            float vo = mo + lg2((ex2(ao - mo) + ex2(ae - mo) + ex2(a2 - mo)) * pl);
            // state 2L (final blank), last thread, uses OLD ao
            if (tid == last) {
                float m5 = fmaxf(a5, ao);
                a5 = m5 + lg2((1.0f + ex2(fminf(a5, ao) - m5)) * pb);
            }
            ae = ve;
            ao = vo;

            // publish boundary value for step t+1
            if (w < 7) {
                BAR_SYNC(EMPTY_p);           // consumer done with previous value
                if (lane == 31) bnd[w] = ao;
                BAR_ARRIVE(FULL_p);
            }

            // refill prefetch slot with step t + DPRE
            int tp = t + DPRE; if (tp > il - 1) tp = il - 1;
            rpb[j] = __ldg(pbase + (long long)tp * C);
            rpl[j] = __ldg(plabp + (long long)tp * C);
        }
    }

    // drain: consumers absorb the last published values so barrier state is
    // balanced (producers' final FULL arrivals). Not strictly required for
    // correctness of sA, but keeps every warp past its last arrive.
    if (w > 0) { BAR_SYNC(FULL_c); BAR_ARRIVE(EMPTY_c); }

    // ---- finalize: dump alpha, loss, fused mean via atomic counter ---------
    __syncthreads();
    sA[2 * tid]     = ae;
    sA[2 * tid + 1] = ao;
    if (tid == last) sA[512] = a5;
    __syncthreads();

    if (tid == 0) {
        float e1 = sA[2 * ll - 1];
        float e2 = sA[2 * ll];
        float m  = fmaxf(e1, e2);
        float l2 = m + lg2(ex2(e1 - m) + ex2(e2 - m));
        g_loss[b] = -l2 * LN2F;
        __threadfence();
        unsigned int old = atomicInc(&g_ctr, (unsigned)(B - 1));   // wraps to 0
        if (old == (unsigned)(B - 1)) {
            __threadfence();
            volatile float* gl = g_loss;
            float s = 0.f;
            for (int i = 0; i < B; ++i) s += gl[i];
            out[loss_idx] = s / (float)B;
        }
    }
}

// ---------------------------------------------------------------------------
extern "C" void kernel_launch(void* const* d_in, const int* in_sizes, int n_in,
                              void* d_out, int out_size) {
    const int*   y_true = (const int*)  d_in[0];  // [B, L]
    const float* y_pred = (const float*)d_in[1];  // [B, T, C]
    const int*   il     = (const int*)  d_in[2];  // [B]
    const int*   ll     = (const int*)  d_in[3];  // [B]

    const int B = in_sizes[2];
    const int L = in_sizes[0] / B;                // 256
    const int C = 128;                            // fixed for this problem
    const int T = in_sizes[1] / (B * C);
    float* out = (float*)d_out;

    const int ctcBlocks   = B;                    // one block per batch element
    const int transBlocks = 1408;                 // fill remaining SMs

    ctc_fused_kernel<<<ctcBlocks + transBlocks, L>>>(
        y_pred, y_true, il, ll, out, T, B, C, L,
        ctcBlocks, (long long)out_size - 1);
}

// round 12
// speedup vs baseline: 2.6060x; 1.6922x over previous
#include <cuda_runtime.h>
#include <math.h>

#define NEGV (-1e30f)
#define LN2F 0.6931471805599453f
#define DPRE 8

// scratch (no cudaMalloc allowed)
__device__ float g_alpha[64 * 520];
__device__ float g_beta[64 * 520];
__device__ float g_loss[4096];
__device__ unsigned g_done[4096];   // 2 incs per b per launch, wraps 0->1->0
__device__ unsigned g_ctr;          // B incs per launch, wraps to 0

__device__ __forceinline__ float ex2(float x) {
    float r; asm("ex2.approx.f32 %0, %1;" : "=f"(r) : "f"(x)); return r;
}
__device__ __forceinline__ float lg2(float x) {
    float r; asm("lg2.approx.f32 %0, %1;" : "=f"(r) : "f"(x)); return r;
}

// ---------------------------------------------------------------------------
// Fused kernel (blockDim = 256):
//   blocks [0, B)        : CTC forward half  (t = 0 .. tm)
//   blocks [B, 2B)       : CTC backward half (t = il-1 .. tm)
//   blocks [2B, grid)    : log + transpose  out[t,b,c] = log(p[b,t,c])
// Second finisher of each (fwd, bwd) pair combines: loss = -lse_s(alpha+beta).
// ---------------------------------------------------------------------------
__global__ void __launch_bounds__(256)
ctc_fused_kernel(const float* __restrict__ p,      // [B,T,C]
                 const int* __restrict__ labels,   // [B,L]
                 const int* __restrict__ in_len,   // [B]
                 const int* __restrict__ lab_len,  // [B]
                 float* __restrict__ out,          // [T,B,C] (+ loss at end)
                 int T, int B, int C, int L,
                 long long loss_idx) {
    const int bx = blockIdx.x;
    if (bx >= 2 * B) {
        // ---------------- log + transpose (float4) --------------------------
        const int c4w = C >> 2;
        const long long total4 = (long long)T * B * c4w;
        const float4* __restrict__ p4 = (const float4*)p;
        float4* __restrict__ o4 = (float4*)out;
        const long long stride = (long long)(gridDim.x - 2 * B) * blockDim.x;
        for (long long v = (long long)(bx - 2 * B) * blockDim.x + threadIdx.x;
             v < total4; v += stride) {
            int c4 = (int)(v % c4w);
            long long rr = v / c4w;          // rr = t*B + b
            int b = (int)(rr % B);
            long long t = rr / B;
            float4 x = p4[((long long)b * T + t) * c4w + c4];
            float4 y;
            y.x = __logf(x.x); y.y = __logf(x.y);
            y.z = __logf(x.z); y.w = __logf(x.w);
            o4[v] = y;
        }
        return;
    }

    // Thread tid owns states 2tid (even/blank, ext=0) and 2tid+1 (odd,
    // ext=labels[tid]); last thread also owns state 512 (final blank).
    __shared__ float bndA[2][8];   // fwd: lane31 ao | bwd: lane0 be
    __shared__ float bndB2[2][8];  // bwd: lane0 bo
    __shared__ float red[8];
    __shared__ unsigned sflag;

    const bool isFwd = (bx < B);
    const int b    = isFwd ? bx : bx - B;
    const int tid  = threadIdx.x;
    const int w    = tid >> 5;
    const int lane = tid & 31;
    const int last = blockDim.x - 1;

    int il = in_len[b];  il = il < 1 ? 1 : (il > T ? T : il);
    int ll = lab_len[b]; ll = ll < 1 ? 1 : (ll > L ? L : ll);
    const int tm = (il - 1) >> 1;            // meeting time

    const float* __restrict__ pbase = p + (long long)b * T * C;   // blank col 0

    if (isFwd) {
        // =============== forward half: alpha for t = 0 .. tm ================
        const int  lab  = labels[b * L + tid];
        const bool skip = (tid > 0) && (lab != labels[b * L + tid - 1]);
        const float* __restrict__ plabp = pbase + lab;

        float ae, ao, a5 = NEGV;
        {
            float pb0 = __ldg(pbase);
            float pl0 = __ldg(plabp);
            ae = (tid == 0) ? lg2(pb0) : NEGV;
            ao = (tid == 0) ? lg2(pl0) : NEGV;
            if (lane == 31) bndA[1][w] = ao;     // parity for t=1
        }
        float rpb[DPRE], rpl[DPRE];
        #pragma unroll
        for (int j = 0; j < DPRE; ++j) {
            int tt = 1 + j; if (tt > il - 1) tt = il - 1;
            rpb[j] = __ldg(pbase + (long long)tt * C);
            rpl[j] = __ldg(plabp + (long long)tt * C);
        }
        __syncthreads();

        const int tend = tm + 1;                  // loop t = 1 .. tm
        for (int tb = 1; tb < tend; tb += DPRE) {
            #pragma unroll
            for (int j = 0; j < DPRE; ++j) {
                int t = tb + j;
                if (t >= tend) break;             // uniform across block

                float pb = rpb[j], pl = rpl[j];
                float a_ol = __shfl_up_sync(0xffffffffu, ao, 1);
                if (lane == 0) a_ol = (w > 0) ? bndA[t & 1][w - 1] : NEGV;

                float me = fmaxf(ae, a_ol);
                float ve = me + lg2((1.0f + ex2(fminf(ae, a_ol) - me)) * pb);
                float a2 = skip ? a_ol : NEGV;
                float mo = fmaxf(ao, fmaxf(ae, a2));
                float vo = mo + lg2((ex2(ao - mo) + ex2(ae - mo) + ex2(a2 - mo)) * pl);
                if (tid == last) {
                    float m5 = fmaxf(a5, ao);
                    a5 = m5 + lg2((1.0f + ex2(fminf(a5, ao) - m5)) * pb);
                }
                ae = ve; ao = vo;
                if (lane == 31) bndA[(t + 1) & 1][w] = ao;

                int tp = t + DPRE; if (tp > il - 1) tp = il - 1;
                rpb[j] = __ldg(pbase + (long long)tp * C);
                rpl[j] = __ldg(plabp + (long long)tp * C);
                __syncthreads();
            }
        }
        float* ga = g_alpha + b * 520;
        ga[2 * tid]     = ae;
        ga[2 * tid + 1] = ao;
        if (tid == last) ga[512] = a5;
    } else {
        // =============== backward half: beta for t = il-1 .. tm =============
        // succ(2tid)   = {2tid (blank), 2tid+1 (lab0)}
        // succ(2tid+1) = {2tid+1 (lab0), 2tid+2 (blank), 2tid+3 (labN if !=)}
        // succ(512)    = {512 (blank)}
        const int  lab0  = labels[b * L + tid];
        const int  labNi = (tid < last) ? labels[b * L + tid + 1] : lab0;
        const bool skipN = (tid < last) && (labNi != lab0);
        const float* __restrict__ pl0p = pbase + lab0;
        const float* __restrict__ plNp = pbase + labNi;

        // init at t = il-1: beta = 1 on end states
        float be = (tid == ll)     ? 0.0f : NEGV;   // state 2ll (if ll<256)
        float bo = (tid == ll - 1) ? 0.0f : NEGV;   // state 2ll-1
        float b5 = (ll == 256 && tid == last) ? 0.0f : NEGV;  // state 512 == 2ll
        if (lane == 0 && w > 0) { bndA[0][w] = be; bndB2[0][w] = bo; }

        const int nsteps = il - 1 - tm;           // k = 0 .. nsteps-1, t = il-2-k
        // prefetch: slot j holds probs for time il-1-(kb+j)
        float rqb[DPRE], rq0[DPRE], rqN[DPRE];
        #pragma unroll
        for (int j = 0; j < DPRE; ++j) {
            int tt = il - 1 - j; if (tt < 0) tt = 0;
            rqb[j] = __ldg(pbase + (long long)tt * C);
            rq0[j] = __ldg(pl0p  + (long long)tt * C);
            rqN[j] = __ldg(plNp  + (long long)tt * C);
        }
        __syncthreads();

        for (int kb = 0; kb < nsteps; kb += DPRE) {
            #pragma unroll
            for (int j = 0; j < DPRE; ++j) {
                int k = kb + j;
                if (k >= nsteps) break;           // uniform across block

                float qb = rqb[j], q0 = rq0[j], qN = rqN[j];
                float beN = __shfl_down_sync(0xffffffffu, be, 1);
                float boN = __shfl_down_sync(0xffffffffu, bo, 1);
                if (lane == 31) {
                    if (tid == last) { beN = b5; boN = NEGV; }
                    else { beN = bndA[k & 1][w + 1]; boN = bndB2[k & 1][w + 1]; }
                }

                // even state 2tid
                float m = fmaxf(be, bo);
                float nbe = m + lg2(ex2(be - m) * qb + ex2(bo - m) * q0);
                // odd state 2tid+1
                float a2 = skipN ? boN : NEGV;
                float mN = fmaxf(bo, fmaxf(beN, a2));
                float s3 = ex2(bo - mN) * q0 + ex2(beN - mN) * qb
                         + (skipN ? ex2(boN - mN) * qN : 0.0f);
                float nbo = mN + lg2(s3);
                // state 512
                if (tid == last) b5 = b5 + lg2(qb);
                be = nbe; bo = nbo;
                if (lane == 0 && w > 0) {
                    bndA[(k + 1) & 1][w] = be; bndB2[(k + 1) & 1][w] = bo;
                }

                int tq = il - 1 - (k + DPRE); if (tq < 0) tq = 0;
                rqb[j] = __ldg(pbase + (long long)tq * C);
                rq0[j] = __ldg(pl0p  + (long long)tq * C);
                rqN[j] = __ldg(plNp  + (long long)tq * C);
                __syncthreads();
            }
        }
        float* gb = g_beta + b * 520;
        gb[2 * tid]     = be;
        gb[2 * tid + 1] = bo;
        if (tid == last) gb[512] = b5;
    }

    // ---- rendezvous: second finisher combines ------------------------------
    __threadfence();
    if (tid == 0) sflag = atomicInc(&g_done[b], 1u);
    __syncthreads();
    if (sflag != 1u) return;

    {
        volatile float* ga = g_alpha + b * 520;
        volatile float* gb = g_beta  + b * 520;
        float v1 = ga[tid]       + gb[tid];
        float v2 = ga[tid + 256] + gb[tid + 256];
        float v3 = (tid == 0) ? (ga[512] + gb[512]) : (NEGV + NEGV);

        float m = fmaxf(v1, fmaxf(v2, v3));
        #pragma unroll
        for (int o = 16; o; o >>= 1)
            m = fmaxf(m, __shfl_xor_sync(0xffffffffu, m, o));
        if (lane == 0) red[w] = m;
        __syncthreads();
        float bm = red[0];
        #pragma unroll
        for (int i = 1; i < 8; ++i) bm = fmaxf(bm, red[i]);

        float s = ex2(v1 - bm) + ex2(v2 - bm) + ex2(v3 - bm);
        #pragma unroll
        for (int o = 16; o; o >>= 1)
            s += __shfl_xor_sync(0xffffffffu, s, o);
        __syncthreads();             // red reuse
        if (lane == 0) red[w] = s;
        __syncthreads();

        if (tid == 0) {
            float ssum = 0.f;
            #pragma unroll
            for (int i = 0; i < 8; ++i) ssum += red[i];
            g_loss[b] = -(bm + lg2(ssum)) * LN2F;
            __threadfence();
            unsigned old = atomicInc(&g_ctr, (unsigned)(B - 1));   // wraps to 0
            if (old == (unsigned)(B - 1)) {
                __threadfence();
                volatile float* gl = g_loss;
                float acc = 0.f;
                for (int i = 0; i < B; ++i) acc += gl[i];
                out[loss_idx] = acc / (float)B;
            }
        }
    }
}

// ---------------------------------------------------------------------------
extern "C" void kernel_launch(void* const* d_in, const int* in_sizes, int n_in,
                              void* d_out, int out_size) {
    const int*   y_true = (const int*)  d_in[0];  // [B, L]
    const float* y_pred = (const float*)d_in[1];  // [B, T, C]
    const int*   il     = (const int*)  d_in[2];  // [B]
    const int*   ll     = (const int*)  d_in[3];  // [B]

    const int B = in_sizes[2];
    const int L = in_sizes[0] / B;                // 256
    const int C = 128;                            // fixed for this problem
    const int T = in_sizes[1] / (B * C);
    float* out = (float*)d_out;

    const int transBlocks = 1344;                 // fill remaining SMs

    ctc_fused_kernel<<<2 * B + transBlocks, L>>>(
        y_pred, y_true, il, ll, out, T, B, C, L,
        (long long)out_size - 1);
}

// round 13
// speedup vs baseline: 2.6934x; 1.0335x over previous
#include <cuda_runtime.h>
#include <math.h>

#define NEGV (-1e30f)
#define LN2F 0.6931471805599453f
#define DPRE 8

// scratch (no cudaMalloc allowed)
__device__ float g_alpha[64 * 520];
__device__ float g_beta[64 * 520];
__device__ float g_loss[4096];
__device__ unsigned g_done[4096];   // 2 incs per b per launch, wraps 0->1->0
__device__ unsigned g_ctr;          // B incs per launch, wraps to 0

__device__ __forceinline__ float ex2(float x) {
    float r; asm("ex2.approx.f32 %0, %1;" : "=f"(r) : "f"(x)); return r;
}
__device__ __forceinline__ float lg2(float x) {
    float r; asm("lg2.approx.f32 %0, %1;" : "=f"(r) : "f"(x)); return r;
}

// ---------------------------------------------------------------------------
// Fused kernel (blockDim = 256):
//   blocks [0, B)        : CTC forward half  (t = 0 .. tm)
//   blocks [B, 2B)       : CTC backward half (t = il-1 .. tm)
//   blocks [2B, grid)    : log + transpose  out[t,b,c] = log(p[b,t,c])
// Second finisher of each (fwd, bwd) pair combines: loss = -lse_s(alpha+beta).
// ---------------------------------------------------------------------------
__global__ void __launch_bounds__(256)
ctc_fused_kernel(const float* __restrict__ p,      // [B,T,C]
                 const int* __restrict__ labels,   // [B,L]
                 const int* __restrict__ in_len,   // [B]
                 const int* __restrict__ lab_len,  // [B]
                 float* __restrict__ out,          // [T,B,C] (+ loss at end)
                 int T, int B, int C, int L,
                 long long loss_idx) {
    const int bx = blockIdx.x;
    if (bx >= 2 * B) {
        // ---------------- log + transpose (float4) --------------------------
        const int c4w = C >> 2;
        const long long total4 = (long long)T * B * c4w;
        const float4* __restrict__ p4 = (const float4*)p;
        float4* __restrict__ o4 = (float4*)out;
        const long long stride = (long long)(gridDim.x - 2 * B) * blockDim.x;
        for (long long v = (long long)(bx - 2 * B) * blockDim.x + threadIdx.x;
             v < total4; v += stride) {
            int c4 = (int)(v % c4w);
            long long rr = v / c4w;          // rr = t*B + b
            int b = (int)(rr % B);
            long long t = rr / B;
            float4 x = p4[((long long)b * T + t) * c4w + c4];
            float4 y;
            y.x = __logf(x.x); y.y = __logf(x.y);
            y.z = __logf(x.z); y.w = __logf(x.w);
            o4[v] = y;
        }
        return;
    }

    __shared__ float bnd[2][8];
    __shared__ float red[8];
    __shared__ unsigned sflag;

    const bool isFwd = (bx < B);
    const int b    = isFwd ? bx : bx - B;
    const int tid  = threadIdx.x;
    const int w    = tid >> 5;
    const int lane = tid & 31;
    const int last = blockDim.x - 1;

    int il = in_len[b];  il = il < 1 ? 1 : (il > T ? T : il);
    int ll = lab_len[b]; ll = ll < 1 ? 1 : (ll > L ? L : ll);
    const int tm = (il - 1) >> 1;            // meeting time

    const float* __restrict__ pbase = p + (long long)b * T * C;   // blank col 0

    if (isFwd) {
        // ===== forward: thread owns alpha(2tid)=ae, alpha(2tid+1)=ao ========
        // dep: left neighbor's old ao (state 2tid-1); last thread owns 512.
        const int   lab = labels[b * L + tid];
        const float ks  = ((tid > 0) && (lab != labels[b * L + tid - 1])) ? 1.0f : 0.0f;
        const float* __restrict__ plabp = pbase + lab;

        float ae, ao, a5 = NEGV;
        {
            float pb0 = __ldg(pbase);
            float pl0 = __ldg(plabp);
            ae = (tid == 0) ? lg2(pb0) : NEGV;
            ao = (tid == 0) ? lg2(pl0) : NEGV;
            if (lane == 31) bnd[1][w] = ao;     // parity for t=1
        }
        float rpb[DPRE], rpl[DPRE];
        #pragma unroll
        for (int j = 0; j < DPRE; ++j) {
            int tt = 1 + j; if (tt > il - 1) tt = il - 1;
            rpb[j] = __ldg(pbase + (long long)tt * C);
            rpl[j] = __ldg(plabp + (long long)tt * C);
        }
        __syncthreads();

        const int tend = tm + 1;                  // loop t = 1 .. tm
        for (int tb = 1; tb < tend; tb += DPRE) {
            #pragma unroll
            for (int j = 0; j < DPRE; ++j) {
                int t = tb + j;
                if (t >= tend) break;             // uniform across block

                float pb = rpb[j], pl = rpl[j];
                float a_ol = __shfl_up_sync(0xffffffffu, ao, 1);
                if (lane == 0) a_ol = (w > 0) ? bnd[t & 1][w - 1] : NEGV;

                // shared max across both lse's
                float m  = fmaxf(fmaxf(ae, ao), a_ol);
                float xe = ex2(ae - m);
                float xo = ex2(ao - m);
                float xL = ex2(a_ol - m);
                float ve = m + lg2((xe + xL) * pb);
                float vo = m + lg2((xo + xe + ks * xL) * pl);
                if (tid == last) {                 // state 512, uses OLD ao
                    float m5 = fmaxf(a5, ao);
                    a5 = fmaxf(m5 + lg2((ex2(a5 - m5) + ex2(ao - m5)) * pb), NEGV);
                }
                ae = fmaxf(ve, NEGV);
                ao = fmaxf(vo, NEGV);
                if (lane == 31) bnd[(t + 1) & 1][w] = ao;

                int tp = t + DPRE; if (tp > il - 1) tp = il - 1;
                rpb[j] = __ldg(pbase + (long long)tp * C);
                rpl[j] = __ldg(plabp + (long long)tp * C);
                __syncthreads();
            }
        }
        float* ga = g_alpha + b * 520;
        ga[2 * tid]     = ae;
        ga[2 * tid + 1] = ao;
        if (tid == last) ga[512] = a5;
    } else {
        // ===== backward: thread owns beta(2tid+1)=bo, beta(2tid+2)=be =======
        // succ(2i+1) = {2i+1 (lab i), 2i+2 (blank), 2i+3 (lab i+1) if !=}
        // succ(2i+2) = {2i+2 (blank), 2i+3 (lab i+1)}   [unconditional]
        // dep: right neighbor's old bo (state 2tid+3). Thread 0 also owns
        // beta(0)=b0 (succ {0 (blank), 1 (lab 0)}).
        const int   lab0 = labels[b * L + tid];
        const int   labN = (tid < last) ? labels[b * L + tid + 1] : lab0;
        const float ksN  = ((tid < last) && (labN != lab0)) ? 1.0f : 0.0f;
        const float* __restrict__ pl0p = pbase + lab0;
        const float* __restrict__ plNp = pbase + labN;

        // init at t = il-1: beta=1 on states {2ll-1, 2ll} -> thread ll-1
        float bo = (tid == ll - 1) ? 0.0f : NEGV;   // state 2tid+1
        float be = (tid == ll - 1) ? 0.0f : NEGV;   // state 2tid+2
        float b0 = NEGV;                             // state 0 (thread 0)
        if (lane == 0 && w > 0) bnd[0][w] = bo;      // consumed at k=0 by w-1

        const int nsteps = il - 1 - tm;           // k = 0 .. nsteps-1
        // slot j holds probs for time il-1-(kb+j)  (beta(t) uses probs at t+1)
        float rqb[DPRE], rq0[DPRE], rqN[DPRE];
        #pragma unroll
        for (int j = 0; j < DPRE; ++j) {
            int tt = il - 1 - j; if (tt < 0) tt = 0;
            rqb[j] = __ldg(pbase + (long long)tt * C);
            rq0[j] = __ldg(pl0p  + (long long)tt * C);
            rqN[j] = __ldg(plNp  + (long long)tt * C);
        }
        __syncthreads();

        for (int kb = 0; kb < nsteps; kb += DPRE) {
            #pragma unroll
            for (int j = 0; j < DPRE; ++j) {
                int k = kb + j;
                if (k >= nsteps) break;           // uniform across block

                float qb = rqb[j], q0 = rq0[j], qN = rqN[j];
                float boN = __shfl_down_sync(0xffffffffu, bo, 1);
                if (lane == 31) boN = (w < 7) ? bnd[k & 1][w + 1] : NEGV;

                float m  = fmaxf(fmaxf(bo, be), boN);
                float xo = ex2(bo - m);
                float xe = ex2(be - m);
                float xN = ex2(boN - m);
                float t1 = xe * qb;
                float t2 = xN * qN;
                float nbo = m + lg2(xo * q0 + t1 + ksN * t2);
                float nbe = m + lg2(t1 + t2);
                if (tid == 0) {                    // state 0, uses OLD bo
                    float mb = fmaxf(b0, bo);
                    b0 = fmaxf(mb + lg2(ex2(b0 - mb) * qb + ex2(bo - mb) * q0), NEGV);
                }
                bo = fmaxf(nbo, NEGV);
                be = fmaxf(nbe, NEGV);
                if (lane == 0 && w > 0) bnd[(k + 1) & 1][w] = bo;

                int tq = il - 1 - (k + DPRE); if (tq < 0) tq = 0;
                rqb[j] = __ldg(pbase + (long long)tq * C);
                rq0[j] = __ldg(pl0p  + (long long)tq * C);
                rqN[j] = __ldg(plNp  + (long long)tq * C);
                __syncthreads();
            }
        }
        float* gb = g_beta + b * 520;
        gb[2 * tid + 1] = bo;
        gb[2 * tid + 2] = be;
        if (tid == 0) gb[0] = b0;
    }

    // ---- rendezvous: second finisher combines ------------------------------
    __threadfence();
    if (tid == 0) sflag = atomicInc(&g_done[b], 1u);
    __syncthreads();
    if (sflag != 1u) return;

    {
        volatile float* ga = g_alpha + b * 520;
        volatile float* gb = g_beta  + b * 520;
        float v1 = ga[tid]       + gb[tid];
        float v2 = ga[tid + 256] + gb[tid + 256];
        float v3 = (tid == 0) ? (ga[512] + gb[512]) : (NEGV + NEGV);

        float m = fmaxf(v1, fmaxf(v2, v3));
        #pragma unroll
        for (int o = 16; o; o >>= 1)
            m = fmaxf(m, __shfl_xor_sync(0xffffffffu, m, o));
        if (lane == 0) red[w] = m;
        __syncthreads();
        float bm = red[0];
        #pragma unroll
        for (int i = 1; i < 8; ++i) bm = fmaxf(bm, red[i]);

        float s = ex2(v1 - bm) + ex2(v2 - bm) + ex2(v3 - bm);
        #pragma unroll
        for (int o = 16; o; o >>= 1)
            s += __shfl_xor_sync(0xffffffffu, s, o);
        __syncthreads();             // red reuse
        if (lane == 0) red[w] = s;
        __syncthreads();

        if (tid == 0) {
            float ssum = 0.f;
            #pragma unroll
            for (int i = 0; i < 8; ++i) ssum += red[i];
            g_loss[b] = -(bm + lg2(ssum)) * LN2F;
            __threadfence();
            unsigned old = atomicInc(&g_ctr, (unsigned)(B - 1));   // wraps to 0
            if (old == (unsigned)(B - 1)) {
                __threadfence();
                volatile float* gl = g_loss;
                float acc = 0.f;
                for (int i = 0; i < B; ++i) acc += gl[i];
                out[loss_idx] = acc / (float)B;
            }
        }
    }
}

// ---------------------------------------------------------------------------
extern "C" void kernel_launch(void* const* d_in, const int* in_sizes, int n_in,
                              void* d_out, int out_size) {
    const int*   y_true = (const int*)  d_in[0];  // [B, L]
    const float* y_pred = (const float*)d_in[1];  // [B, T, C]
    const int*   il     = (const int*)  d_in[2];  // [B]
    const int*   ll     = (const int*)  d_in[3];  // [B]

    const int B = in_sizes[2];
    const int L = in_sizes[0] / B;                // 256
    const int C = 128;                            // fixed for this problem
    const int T = in_sizes[1] / (B * C);
    float* out = (float*)d_out;

    const int transBlocks = 1344;                 // fill remaining SMs

    ctc_fused_kernel<<<2 * B + transBlocks, L>>>(
        y_pred, y_true, il, ll, out, T, B, C, L,
        (long long)out_size - 1);
}